// round 17
// baseline (speedup 1.0000x reference)
#include <cuda_runtime.h>
#include <cuda_bf16.h>
#include <cuda_fp16.h>
#include <math.h>
#include <stdint.h>

static constexpr int B_ = 8;
static constexpr int C_ = 256;
static constexpr int N_ = 2048;
static constexpr int M_ = 2048;

// Scratch (no cudaMalloc allowed) — fp16/bf16 pairs stored as u32
__device__ uint32_t g_d1p[8*128*2048];   // desc1 fp16 (k,k+8)-pairs
__device__ uint32_t g_d2p[8*128*2048];
__device__ uint32_t g_wqp[256*128];      // weights fp16 A-pairs (perm16'd)
__device__ uint32_t g_wkp[256*128];
__device__ uint32_t g_wvp[256*128];
__device__ uint32_t g_wc2p[256*256];
__device__ uint32_t g_wfp[512*256];      // fused Wc1' fp16 pairs (perm16'd)
__device__ uint32_t g_wc1bp[512*128];    // Wc1[:,256:] A-pairs (perm16'd)
__device__ uint32_t g_wmp[128*256];      // Wm B-pairs (NOT permuted)
__device__ float    g_bfv[512];          // fused bias
__device__ uint32_t g_qp[B_*4*32*2048];  // bf16 attention operands
__device__ uint32_t g_kp[B_*4*32*2048];
__device__ uint32_t g_vp[B_*4*64*1024];
__device__ uint32_t g_attp[8*128*2048];  // attention out, fp16 pairs
__device__ uint32_t g_hp[8*256*2048];    // h, fp16 pairs

// ---------------------------------------------------------------------------
// helpers
// ---------------------------------------------------------------------------
__device__ __forceinline__ uint32_t s2u(const void* p) {
    return (uint32_t)__cvta_generic_to_shared(p);
}
#define CPA16(dst, src) \
    asm volatile("cp.async.cg.shared.global [%0], [%1], 16;" :: "r"(dst), "l"(src))
#define CPA_COMMIT() asm volatile("cp.async.commit_group;")
#define CPA_WAIT0()  asm volatile("cp.async.wait_group 0;")
#define CPA_WAIT1()  asm volatile("cp.async.wait_group 1;")

__device__ __forceinline__ void mma_bf16(
    float d[4], const uint32_t a[4], uint32_t b0, uint32_t b1, const float c[4])
{
    asm volatile(
        "mma.sync.aligned.m16n8k16.row.col.f32.bf16.bf16.f32 "
        "{%0,%1,%2,%3}, {%4,%5,%6,%7}, {%8,%9}, {%10,%11,%12,%13};"
        : "=f"(d[0]), "=f"(d[1]), "=f"(d[2]), "=f"(d[3])
        : "r"(a[0]), "r"(a[1]), "r"(a[2]), "r"(a[3]),
          "r"(b0), "r"(b1),
          "f"(c[0]), "f"(c[1]), "f"(c[2]), "f"(c[3]));
}
__device__ __forceinline__ void mma_f16(
    float d[4], const uint32_t a[4], uint32_t b0, uint32_t b1, const float c[4])
{
    asm volatile(
        "mma.sync.aligned.m16n8k16.row.col.f32.f16.f16.f32 "
        "{%0,%1,%2,%3}, {%4,%5,%6,%7}, {%8,%9}, {%10,%11,%12,%13};"
        : "=f"(d[0]), "=f"(d[1]), "=f"(d[2]), "=f"(d[3])
        : "r"(a[0]), "r"(a[1]), "r"(a[2]), "r"(a[3]),
          "r"(b0), "r"(b1),
          "f"(c[0]), "f"(c[1]), "f"(c[2]), "f"(c[3]));
}
__device__ __forceinline__ uint32_t pkbf(float lo, float hi) {
    __nv_bfloat162 h = __floats2bfloat162_rn(lo, hi);
    return *(uint32_t*)&h;
}
__device__ __forceinline__ uint32_t pkhf(float lo, float hi) {
    __half2 h = __floats2half2_rn(lo, hi);
    return *(uint32_t*)&h;
}
// within-16-chunk column permutation so A-fragments are LDS.128-contiguous
__device__ __forceinline__ int perm16(int kp) {
    return (kp & ~15) | (((kp & 3) << 2) | ((kp >> 2) & 3));
}

// ---------------------------------------------------------------------------
// Pre-pass: fp16 pair-pack conversions (+perm16 on weight columns) + bias.
// Pair convention: kp -> k = 16*(kp>>3) + (kp&7), pair (k, k+8).
// ---------------------------------------------------------------------------
__global__ void __launch_bounds__(256) prepass(
    const float* __restrict__ desc1, const float* __restrict__ desc2,
    const float* __restrict__ Wq, const float* __restrict__ Wk,
    const float* __restrict__ Wv, const float* __restrict__ Wc2,
    const float* __restrict__ Wc1, const float* __restrict__ Wm,
    const float* __restrict__ bm, const float* __restrict__ bc1,
    uint32_t* __restrict__ d1p, uint32_t* __restrict__ d2p,
    uint32_t* __restrict__ wqp, uint32_t* __restrict__ wkp,
    uint32_t* __restrict__ wvp, uint32_t* __restrict__ wc2p,
    uint32_t* __restrict__ wfp, uint32_t* __restrict__ wc1bp,
    uint32_t* __restrict__ wmp, float* __restrict__ bfv)
{
    int x = blockIdx.x;
    const int t = threadIdx.x;

    if (x < 2048) {  // desc1 / desc2 rows (unchanged)
        const float* src = (x < 1024) ? desc1 : desc2;
        uint32_t* dst = (x < 1024) ? d1p : d2p;
        int xi = x & 1023;
        int b = xi >> 7, kp = xi & 127;
        int k = 16*(kp>>3) + (kp&7);
        const float* r0 = src + ((size_t)b*256 + k) * 2048;
        const float* r1 = r0 + 8*2048;
        uint32_t* o = dst + ((size_t)b*128 + kp) * 2048;
        for (int c = t*4; c < 2048; c += 1024) {
            float4 a  = *(const float4*)&r0[c];
            float4 bb = *(const float4*)&r1[c];
            *(uint4*)&o[c] = make_uint4(pkhf(a.x,bb.x), pkhf(a.y,bb.y),
                                        pkhf(a.z,bb.z), pkhf(a.w,bb.w));
        }
        return;
    }
    x -= 2048;
    if (x < 768) {  // Wq/Wk/Wv rows (Kd=256) — perm16
        const float* W = (x < 256) ? Wq : (x < 512) ? Wk : Wv;
        uint32_t* o    = (x < 256) ? wqp : (x < 512) ? wkp : wvp;
        int row = x & 255;
        for (int kp = t; kp < 128; kp += 256) {
            int k = 16*(kp>>3) + (kp&7);
            o[row*128 + perm16(kp)] = pkhf(W[row*256 + k], W[row*256 + k + 8]);
        }
        return;
    }
    x -= 768;
    if (x < 256) {  // Wc2 rows (Kd=512) — perm16
        for (int kp = t; kp < 256; kp += 256) {
            int k = 16*(kp>>3) + (kp&7);
            wc2p[x*256 + perm16(kp)] = pkhf(Wc2[x*512 + k], Wc2[x*512 + k + 8]);
        }
        return;
    }
    x -= 256;
    if (x < 512) {  // Wc1a -> Wf[:, 0:128] — perm16
        for (int kp = t; kp < 128; kp += 256) {
            int k = 16*(kp>>3) + (kp&7);
            wfp[x*256 + perm16(kp)] = pkhf(Wc1[x*512 + k], Wc1[x*512 + k + 8]);
        }
        return;
    }
    x -= 512;
    if (x < 512) {  // Wc1b A-pairs — perm16
        for (int kp = t; kp < 128; kp += 256) {
            int k = 16*(kp>>3) + (kp&7);
            wc1bp[x*128 + perm16(kp)] =
                pkhf(Wc1[x*512 + 256 + k], Wc1[x*512 + 256 + k + 8]);
        }
        return;
    }
    x -= 512;
    if (x < 128) {  // Wm B-pairs (X-side, NOT permuted)
        int k = 16*(x>>3) + (x&7);
        for (int i = t; i < 256; i += 256)
            wmp[x*256 + i] = pkhf(Wm[k*256 + i], Wm[(k+8)*256 + i]);
        return;
    }
    x -= 128;
    if (x < 2) {  // bf = bc1 + Wc1b @ bm (fp32)
        int row = x*256 + t;
        float s = 0.f;
        const float* wr = Wc1 + (size_t)row*512 + 256;
        #pragma unroll 4
        for (int j = 0; j < 256; j++) s += wr[j] * bm[j];
        bfv[row] = bc1[row] + s;
    }
}

// ---------------------------------------------------------------------------
// fp16 GEMM tile geometry: 64 o x 128 n, chunk 32 k (16 pair-cols), 3-stage.
// W chunk smem [64][16] u32 (perm16'd; LDS.128 A-frags conflict-free),
// X chunk smem [16][136] u32.
// ---------------------------------------------------------------------------
static constexpr int WCH = 64*16;       // 1024 u32 per W buffer
static constexpr int XP_ST = 136;
static constexpr int XCH = 16*XP_ST;    // 2176 u32 per X buffer
static constexpr int GEMM_SMEM_H = (3*WCH + 3*XCH) * 4;  // 38400 B

// compute one 32-k chunk given smem buffers (shared by all GEMM kernels)
#define GEMM_CHUNK(MMA)                                                        \
    do {                                                                       \
        uint32_t a2[2][2][4];                                                  \
        _Pragma("unroll")                                                      \
        for (int st = 0; st < 2; st++) {                                       \
            uint4 wg = *(const uint4*)&Wc[(ow + 16*st + g    )*16 + 4*q4];     \
            uint4 wh = *(const uint4*)&Wc[(ow + 16*st + g + 8)*16 + 4*q4];     \
            a2[st][0][0]=wg.x; a2[st][0][1]=wh.x; a2[st][0][2]=wg.y; a2[st][0][3]=wh.y; \
            a2[st][1][0]=wg.z; a2[st][1][1]=wh.z; a2[st][1][2]=wg.w; a2[st][1][3]=wh.w; \
        }                                                                      \
        _Pragma("unroll")                                                      \
        for (int dc = 0; dc < 2; dc++) {                                       \
            const uint32_t* x0 = &Xc[(8*dc + q4    )*XP_ST + nwp + g];         \
            const uint32_t* x1 = &Xc[(8*dc + q4 + 4)*XP_ST + nwp + g];         \
            _Pragma("unroll")                                                  \
            for (int nc = 0; nc < 8; nc++) {                                   \
                uint32_t b0 = x0[8*nc], b1 = x1[8*nc];                         \
                MMA(acc[0][nc], a2[0][dc], b0, b1, acc[0][nc]);                \
                MMA(acc[1][nc], a2[1][dc], b0, b1, acc[1][nc]);                \
            }                                                                  \
        }                                                                      \
    } while (0)

// ---------------------------------------------------------------------------
// Fused Q/K/V projection (fp16, 3-stage) + Wf2 prep GEMM (z == 24).
// ---------------------------------------------------------------------------
__global__ void __launch_bounds__(128, 4) gemm_qkv(
    const uint32_t* __restrict__ wqp, const float* __restrict__ bq,
    const uint32_t* __restrict__ wkp, const float* __restrict__ bk,
    const uint32_t* __restrict__ wvp, const float* __restrict__ bv,
    const uint32_t* __restrict__ d1p, const uint32_t* __restrict__ d2p,
    const float* __restrict__ wv,
    uint32_t* __restrict__ qp, uint32_t* __restrict__ kp, uint32_t* __restrict__ vp,
    const uint32_t* __restrict__ wc1bp, const uint32_t* __restrict__ wmp,
    uint32_t* __restrict__ wfp)
{
    extern __shared__ uint32_t sgu[];

    const int t  = threadIdx.x;
    const int lane = t & 31, w = t >> 5;
    const int g = lane >> 2, q4 = lane & 3;
    const int ow = (w & 1) * 32;
    const int nwp = (w >> 1) * 64;

    float acc[2][8][4];
    #pragma unroll
    for (int st = 0; st < 2; st++)
        #pragma unroll
        for (int nc = 0; nc < 8; nc++)
            #pragma unroll
            for (int j = 0; j < 4; j++) acc[st][nc][j] = 0.f;

    // ======================= PREP SLICE (z == 24) =======================
    if (blockIdx.z == 24) {
        const int cid = blockIdx.y * gridDim.x + blockIdx.x;
        if (cid >= 16) return;
        const int o0 = (cid >> 1) * 64;
        const int i0 = (cid & 1) * 128;

        auto issueP = [&](int c0, int bj) {
            uint32_t* Wd = sgu + bj*WCH;
            uint32_t* Xd = sgu + 3*WCH + bj*XCH;
            #pragma unroll
            for (int r = 0; r < 2; r++) {
                int ch = r*128 + t, row = ch >> 2, q = (ch & 3) << 2;
                CPA16(s2u(Wd + row*16 + q), wc1bp + (size_t)(o0+row)*128 + c0 + q);
            }
            #pragma unroll
            for (int r = 0; r < 4; r++) {
                int ch = r*128 + t, row = ch >> 5, c4 = (ch & 31) << 2;
                CPA16(s2u(Xd + row*XP_ST + c4), wmp + (size_t)(c0+row)*256 + i0 + c4);
            }
            CPA_COMMIT();
        };

        issueP(0, 0);
        issueP(16, 1);
        int bi = 0, bj = 2;
        for (int i = 0; i < 8; i++) {
            if (i + 1 < 8) { CPA_WAIT1(); } else { CPA_WAIT0(); }
            __syncthreads();
            if (i + 2 < 8) { issueP((i + 2) * 16, bj); if (++bj == 3) bj = 0; }
            const uint32_t* Wc = sgu + bi*WCH;
            const uint32_t* Xc = sgu + 3*WCH + bi*XCH;
            GEMM_CHUNK(mma_f16);
            if (++bi == 3) bi = 0;
        }
        // pairs along output n -> Wf[:, perm16(128 + kpc)]
        #pragma unroll
        for (int st = 0; st < 2; st++) {
            const int row0 = o0 + ow + 16*st + g;
            const int row1 = row0 + 8;
            #pragma unroll
            for (int nc = 0; nc < 8; nc += 2) {
                const int n = i0 + nwp + 8*nc + 2*q4;
                const int kpc = 128 + ((n >> 4) << 3) + (n & 7);
                wfp[(size_t)row0*256 + perm16(kpc    )] = pkhf(acc[st][nc][0], acc[st][nc+1][0]);
                wfp[(size_t)row0*256 + perm16(kpc + 1)] = pkhf(acc[st][nc][1], acc[st][nc+1][1]);
                wfp[(size_t)row1*256 + perm16(kpc    )] = pkhf(acc[st][nc][2], acc[st][nc+1][2]);
                wfp[(size_t)row1*256 + perm16(kpc + 1)] = pkhf(acc[st][nc][3], acc[st][nc+1][3]);
            }
        }
        return;
    }

    // ======================= Q/K/V PROJECTIONS =======================
    const int p  = blockIdx.z >> 3;
    const int b  = blockIdx.z & 7;
    const uint32_t* W    = (p == 0) ? wqp : (p == 1) ? wkp : wvp;
    const float* bias    = (p == 0) ? bq : (p == 1) ? bk : bv;
    const uint32_t* X    = ((p == 0) ? d1p : d2p) + (size_t)b*128*2048;
    uint32_t* Yp         = (p == 0) ? qp : (p == 1) ? kp : vp;

    const int o0 = blockIdx.y * 64;
    const int n0 = blockIdx.x * 128;

    auto issue = [&](int c0, int bj) {
        uint32_t* Wd = sgu + bj*WCH;
        uint32_t* Xd = sgu + 3*WCH + bj*XCH;
        #pragma unroll
        for (int r = 0; r < 2; r++) {
            int ch = r*128 + t, row = ch >> 2, q = (ch & 3) << 2;
            CPA16(s2u(Wd + row*16 + q), W + (size_t)(o0+row)*128 + c0 + q);
        }
        #pragma unroll
        for (int r = 0; r < 4; r++) {
            int ch = r*128 + t, row = ch >> 5, c4 = (ch & 31) << 2;
            CPA16(s2u(Xd + row*XP_ST + c4), X + (size_t)(c0+row)*2048 + n0 + c4);
        }
        CPA_COMMIT();
    };

    issue(0, 0);
    issue(16, 1);
    int bi = 0, bj = 2;
    for (int i = 0; i < 8; i++) {
        if (i + 1 < 8) { CPA_WAIT1(); } else { CPA_WAIT0(); }
        __syncthreads();
        if (i + 2 < 8) { issue((i + 2) * 16, bj); if (++bj == 3) bj = 0; }
        const uint32_t* Wc = sgu + bi*WCH;
        const uint32_t* Xc = sgu + 3*WCH + bi*XCH;
        GEMM_CHUNK(mma_f16);
        if (++bi == 3) bi = 0;
    }

    // ---- Epilogue: bf16 pack for attention (unchanged mapping) ----
    #pragma unroll
    for (int st = 0; st < 2; st++) {
        const int row0 = o0 + ow + 16*st + g;
        const int row1 = row0 + 8;
        const float bi0 = bias[row0];
        const float bi1 = bias[row1];
        const int d0 = row0 & 63, h = row0 >> 6;

        if (p < 2) {
            const size_t obase =
                (((size_t)b*4 + h)*32 + ((d0 >> 4)*8 + (d0 & 7))) * (size_t)N_;
            #pragma unroll
            for (int nc = 0; nc < 8; nc++) {
                const int n = n0 + nwp + 8*nc + 2*q4;
                Yp[obase + n    ] = pkbf(acc[st][nc][0] + bi0, acc[st][nc][2] + bi1);
                Yp[obase + n + 1] = pkbf(acc[st][nc][1] + bi0, acc[st][nc][3] + bi1);
            }
        } else {
            const size_t b0v = (((size_t)b*4 + h)*64 + d0    ) * (size_t)(N_/2);
            const size_t b1v = (((size_t)b*4 + h)*64 + d0 + 8) * (size_t)(N_/2);
            #pragma unroll
            for (int nc = 0; nc < 8; nc++) {
                const int n = n0 + nwp + 8*nc + 2*q4;
                float2 wv2 = *(const float2*)&wv[(size_t)b * N_ + n];
                Yp[b0v + (n >> 1)] = pkbf((acc[st][nc][0] + bi0) * wv2.x,
                                          (acc[st][nc][1] + bi0) * wv2.y);
                Yp[b1v + (n >> 1)] = pkbf((acc[st][nc][2] + bi1) * wv2.x,
                                          (acc[st][nc][3] + bi1) * wv2.y);
            }
        }
    }
}

// ---------------------------------------------------------------------------
// fp16 GEMM with fused epilogue (3-stage).
// MODE 2: BN+ReLU -> fp16 pairs Hp.   MODE 3: +residual -> fp32 Y.
// ---------------------------------------------------------------------------
template<int MODE>
__global__ void __launch_bounds__(128, 4) gemm_h(
    const uint32_t* __restrict__ Wp, const float* __restrict__ bias,
    const uint32_t* __restrict__ Xa, const uint32_t* __restrict__ Xb,
    float* __restrict__ Y, uint32_t* __restrict__ Hp,
    int Cout, int Kp, int Cap,
    const float* __restrict__ e0, const float* __restrict__ e1,
    const float* __restrict__ e2, const float* __restrict__ e3)
{
    extern __shared__ uint32_t sgu[];

    const int b  = blockIdx.z;
    const int o0 = blockIdx.y * 64;
    const int n0 = blockIdx.x * 128;
    const int t  = threadIdx.x;
    const int lane = t & 31, w = t >> 5;
    const int g = lane >> 2, q4 = lane & 3;
    const int ow = (w & 1) * 32;
    const int nwp = (w >> 1) * 64;

    const uint32_t* XaB = Xa + (size_t)b * Cap * 2048;
    const uint32_t* XbB = Xb + (size_t)b * (Kp - Cap) * 2048;

    auto issue = [&](int c0, int bj) {
        uint32_t* Wd = sgu + bj*WCH;
        uint32_t* Xd = sgu + 3*WCH + bj*XCH;
        #pragma unroll
        for (int r = 0; r < 2; r++) {
            int ch = r*128 + t, row = ch >> 2, q = (ch & 3) << 2;
            CPA16(s2u(Wd + row*16 + q), Wp + (size_t)(o0+row)*Kp + c0 + q);
        }
        #pragma unroll
        for (int r = 0; r < 4; r++) {
            int ch = r*128 + t, row = ch >> 5, c4 = (ch & 31) << 2;
            int ig = c0 + row;
            const uint32_t* src = (ig < Cap)
                ? XaB + (size_t)ig * 2048 + n0 + c4
                : XbB + (size_t)(ig - Cap) * 2048 + n0 + c4;
            CPA16(s2u(Xd + row*XP_ST + c4), src);
        }
        CPA_COMMIT();
    };

    float acc[2][8][4];
    #pragma unroll
    for (int st = 0; st < 2; st++)
        #pragma unroll
        for (int nc = 0; nc < 8; nc++)
            #pragma unroll
            for (int j = 0; j < 4; j++) acc[st][nc][j] = 0.f;

    const int nch = Kp >> 4;
    issue(0, 0);
    issue(16, 1);
    int bi = 0, bj = 2;
    for (int i = 0; i < nch; i++) {
        if (i + 1 < nch) { CPA_WAIT1(); } else { CPA_WAIT0(); }
        __syncthreads();
        if (i + 2 < nch) { issue((i + 2) * 16, bj); if (++bj == 3) bj = 0; }
        const uint32_t* Wc = sgu + bi*WCH;
        const uint32_t* Xc = sgu + 3*WCH + bi*XCH;
        GEMM_CHUNK(mma_f16);
        if (++bi == 3) bi = 0;
    }

    #pragma unroll
    for (int st = 0; st < 2; st++) {
        const int row0 = o0 + ow + 16*st + g;
        const int row1 = row0 + 8;
        const float bi0 = bias[row0];
        const float bi1 = bias[row1];

        if constexpr (MODE == 2) {
            float inv0 = e0[row0] * rsqrtf(e3[row0] + 1e-5f);
            float add0 = e1[row0] - e2[row0] * inv0;
            float inv1 = e0[row1] * rsqrtf(e3[row1] + 1e-5f);
            float add1 = e1[row1] - e2[row1] * inv1;
            const int kpo = ((row0 >> 4) << 3) + g;     // pair (row0,row1)
            uint32_t* orow = Hp + ((size_t)b*(Cout>>1) + kpo) * 2048;
            #pragma unroll
            for (int nc = 0; nc < 8; nc++) {
                const int n = n0 + nwp + 8*nc + 2*q4;
                float y0x = fmaxf(fmaf(acc[st][nc][0] + bi0, inv0, add0), 0.f);
                float y0y = fmaxf(fmaf(acc[st][nc][1] + bi0, inv0, add0), 0.f);
                float y1x = fmaxf(fmaf(acc[st][nc][2] + bi1, inv1, add1), 0.f);
                float y1y = fmaxf(fmaf(acc[st][nc][3] + bi1, inv1, add1), 0.f);
                *(uint2*)&orow[n] = make_uint2(pkhf(y0x, y1x), pkhf(y0y, y1y));
            }
        } else {
            const size_t yb0 = ((size_t)b*Cout + row0) * N_;
            const size_t yb1 = ((size_t)b*Cout + row1) * N_;
            #pragma unroll
            for (int nc = 0; nc < 8; nc++) {
                const int n = n0 + nwp + 8*nc + 2*q4;
                float2 y0 = make_float2(acc[st][nc][0] + bi0, acc[st][nc][1] + bi0);
                float2 y1 = make_float2(acc[st][nc][2] + bi1, acc[st][nc][3] + bi1);
                float2 r0 = *(const float2*)&e0[yb0 + n];
                float2 r1 = *(const float2*)&e0[yb1 + n];
                y0.x += r0.x; y0.y += r0.y;
                y1.x += r1.x; y1.y += r1.y;
                *(float2*)&Y[yb0 + n] = y0;
                *(float2*)&Y[yb1 + n] = y1;
            }
        }
    }
}

// ---------------------------------------------------------------------------
// Attention, bf16 mma, register-resident P, 2 strips/warp (proven R14 core);
// output as fp16 (c, c+8)-pairs into attp. UNCHANGED from R16.
// ---------------------------------------------------------------------------
static constexpr int QS_ST = 136;  // u32
static constexpr int KK_ST = 72;   // u32
static constexpr int VP_ST = 36;   // u32
static constexpr int ATT_SMEM = (32*QS_ST + 2*32*KK_ST + 2*64*VP_ST) * 4;  // 54272 B

__global__ void __launch_bounds__(128) attn_bf16(
    const uint32_t* __restrict__ QP, const uint32_t* __restrict__ KP,
    const uint32_t* __restrict__ VP, uint32_t* __restrict__ ATT)
{
    extern __shared__ uint32_t su[];
    uint32_t* Qs  = su;
    uint32_t* Kb0 = su + 4352;
    uint32_t* Kb1 = su + 6656;
    uint32_t* Vb0 = su + 8960;
    uint32_t* Vb1 = su + 11264;

    const int bh = blockIdx.y;
    const int n0 = blockIdx.x * 128;
    const size_t qkb = (size_t)bh * 32 * 2048;
    const size_t vb  = (size_t)bh * 64 * 1024;
    const int t = threadIdx.x;
    const int lane = t & 31, w = t >> 5;
    const int g = lane >> 2, q4 = lane & 3;
    const int nw = w * 32;

    auto issue_kv = [&](int m0, int bufi) {
        uint32_t* Kd = bufi ? Kb1 : Kb0;
        uint32_t* Vd = bufi ? Vb1 : Vb0;
        #pragma unroll
        for (int r = 0; r < 4; r++) {
            int ch = r*128 + t, row = ch >> 4, c4 = (ch & 15) << 2;
            CPA16(s2u(Kd + row*KK_ST + c4), KP + qkb + (size_t)row*2048 + m0 + c4);
        }
        #pragma unroll
        for (int r = 0; r < 4; r++) {
            int ch = r*128 + t, row = ch >> 3, c4 = (ch & 7) << 2;
            CPA16(s2u(Vd + row*VP_ST + c4), VP + vb + (size_t)row*1024 + (m0 >> 1) + c4);
        }
        CPA_COMMIT();
    };

    #pragma unroll
    for (int r = 0; r < 8; r++) {
        int ch = r*128 + t, row = ch >> 5, c4 = (ch & 31) << 2;
        CPA16(s2u(Qs + row*QS_ST + c4), QP + qkb + (size_t)row*2048 + n0 + c4);
    }
    CPA_COMMIT();
    issue_kv(0, 0);
    CPA_WAIT1();
    __syncthreads();

    uint32_t qa[2][4][4];
    #pragma unroll
    for (int st = 0; st < 2; st++) {
        const int nb = nw + 16*st;
        #pragma unroll
        for (int dc = 0; dc < 4; dc++) {
            qa[st][dc][0] = Qs[(8*dc + q4    )*QS_ST + nb + g];
            qa[st][dc][1] = Qs[(8*dc + q4    )*QS_ST + nb + g + 8];
            qa[st][dc][2] = Qs[(8*dc + q4 + 4)*QS_ST + nb + g];
            qa[st][dc][3] = Qs[(8*dc + q4 + 4)*QS_ST + nb + g + 8];
        }
    }

    float o0_[8][4], o1_[8][4];
    #pragma unroll
    for (int dc = 0; dc < 8; dc++)
        #pragma unroll
        for (int j = 0; j < 4; j++) { o0_[dc][j] = 0.f; o1_[dc][j] = 0.f; }
    float l00 = 0.f, l01 = 0.f, l10 = 0.f, l11 = 0.f;

    for (int i = 0; i < M_/64; i++) {
        CPA_WAIT0();
        __syncthreads();
        if (i + 1 < M_/64) issue_kv((i + 1) * 64, (i + 1) & 1);

        const uint32_t* Kc = (i & 1) ? Kb1 : Kb0;
        const uint32_t* Vc = (i & 1) ? Vb1 : Vb0;

        float s0[8][4], s1[8][4];
        #pragma unroll
        for (int mc = 0; mc < 8; mc++)
            #pragma unroll
            for (int j = 0; j < 4; j++) { s0[mc][j] = 0.f; s1[mc][j] = 0.f; }

        #pragma unroll
        for (int dc = 0; dc < 4; dc++) {
            const uint32_t* k0 = &Kc[(8*dc + q4    )*KK_ST + g];
            const uint32_t* k1 = &Kc[(8*dc + q4 + 4)*KK_ST + g];
            #pragma unroll
            for (int mc = 0; mc < 8; mc++) {
                uint32_t b0 = k0[8*mc], b1 = k1[8*mc];
                mma_bf16(s0[mc], qa[0][dc], b0, b1, s0[mc]);
                mma_bf16(s1[mc], qa[1][dc], b0, b1, s1[mc]);
            }
        }

        uint32_t pa0[4][4], pa1[4][4];
        #pragma unroll
        for (int mc = 0; mc < 8; mc++) {
            s0[mc][0] = __expf(s0[mc][0] * 0.125f);
            s0[mc][1] = __expf(s0[mc][1] * 0.125f);
            s0[mc][2] = __expf(s0[mc][2] * 0.125f);
            s0[mc][3] = __expf(s0[mc][3] * 0.125f);
            l00 += s0[mc][0] + s0[mc][1];
            l01 += s0[mc][2] + s0[mc][3];
            s1[mc][0] = __expf(s1[mc][0] * 0.125f);
            s1[mc][1] = __expf(s1[mc][1] * 0.125f);
            s1[mc][2] = __expf(s1[mc][2] * 0.125f);
            s1[mc][3] = __expf(s1[mc][3] * 0.125f);
            l10 += s1[mc][0] + s1[mc][1];
            l11 += s1[mc][2] + s1[mc][3];
        }
        #pragma unroll
        for (int mkc = 0; mkc < 4; mkc++) {
            pa0[mkc][0] = pkbf(s0[2*mkc  ][0], s0[2*mkc  ][1]);
            pa0[mkc][1] = pkbf(s0[2*mkc  ][2], s0[2*mkc  ][3]);
            pa0[mkc][2] = pkbf(s0[2*mkc+1][0], s0[2*mkc+1][1]);
            pa0[mkc][3] = pkbf(s0[2*mkc+1][2], s0[2*mkc+1][3]);
            pa1[mkc][0] = pkbf(s1[2*mkc  ][0], s1[2*mkc  ][1]);
            pa1[mkc][1] = pkbf(s1[2*mkc  ][2], s1[2*mkc  ][3]);
            pa1[mkc][2] = pkbf(s1[2*mkc+1][0], s1[2*mkc+1][1]);
            pa1[mkc][3] = pkbf(s1[2*mkc+1][2], s1[2*mkc+1][3]);
        }

        #pragma unroll
        for (int mkc = 0; mkc < 4; mkc++) {
            #pragma unroll
            for (int dc = 0; dc < 8; dc++) {
                const uint32_t* vr = &Vc[(8*dc + g)*VP_ST + 8*mkc];
                uint32_t v0 = vr[q4], v1 = vr[q4 + 4];
                mma_bf16(o0_[dc], pa0[mkc], v0, v1, o0_[dc]);
                mma_bf16(o1_[dc], pa1[mkc], v0, v1, o1_[dc]);
            }
        }
    }

    l00 += __shfl_xor_sync(0xffffffffu, l00, 1);
    l00 += __shfl_xor_sync(0xffffffffu, l00, 2);
    l01 += __shfl_xor_sync(0xffffffffu, l01, 1);
    l01 += __shfl_xor_sync(0xffffffffu, l01, 2);
    l10 += __shfl_xor_sync(0xffffffffu, l10, 1);
    l10 += __shfl_xor_sync(0xffffffffu, l10, 2);
    l11 += __shfl_xor_sync(0xffffffffu, l11, 1);
    l11 += __shfl_xor_sync(0xffffffffu, l11, 2);
    const float i00 = 1.0f / l00, i01 = 1.0f / l01;
    const float i10 = 1.0f / l10, i11 = 1.0f / l11;

    __syncthreads();
    float* Os = (float*)su;
    #pragma unroll
    for (int dc = 0; dc < 8; dc++) {
        #pragma unroll
        for (int j = 0; j < 2; j++) {
            int d = 8*dc + 2*q4 + j;
            Os[d*QS_ST + nw + g         ] = o0_[dc][j]     * i00;
            Os[d*QS_ST + nw + g + 8     ] = o0_[dc][2 + j] * i01;
            Os[d*QS_ST + nw + 16 + g    ] = o1_[dc][j]     * i10;
            Os[d*QS_ST + nw + 16 + g + 8] = o1_[dc][2 + j] * i11;
        }
    }
    __syncthreads();
    const int bb = bh >> 2, hh = bh & 3;
    uint32_t* arow = ATT + ((size_t)bb*128 + 32*hh) * 2048 + n0;
    #pragma unroll
    for (int r = 0; r < 32; r++) {
        int d = 16*(r >> 3) + (r & 7);
        arow[(size_t)r * 2048 + t] = pkhf(Os[d*QS_ST + t], Os[(d+8)*QS_ST + t]);
    }
}

// ---------------------------------------------------------------------------
extern "C" void kernel_launch(void* const* d_in, const int* in_sizes, int n_in,
                              void* d_out, int out_size)
{
    const float* desc1 = (const float*)d_in[0];
    const float* desc2 = (const float*)d_in[1];
    const float* wv    = (const float*)d_in[2];
    const float* Wq    = (const float*)d_in[3];
    const float* bq    = (const float*)d_in[4];
    const float* Wk    = (const float*)d_in[5];
    const float* bk    = (const float*)d_in[6];
    const float* Wv    = (const float*)d_in[7];
    const float* bv    = (const float*)d_in[8];
    const float* Wm    = (const float*)d_in[9];
    const float* bm    = (const float*)d_in[10];
    const float* Wc1   = (const float*)d_in[11];
    const float* bc1   = (const float*)d_in[12];
    const float* gamma = (const float*)d_in[13];
    const float* beta  = (const float*)d_in[14];
    const float* mean  = (const float*)d_in[15];
    const float* var   = (const float*)d_in[16];
    const float* Wc2   = (const float*)d_in[17];
    const float* bc2   = (const float*)d_in[18];
    float* out = (float*)d_out;

    uint32_t *d1p, *d2p, *wqp, *wkp, *wvp, *wc2p, *wfp, *wc1bp, *wmp;
    uint32_t *qp, *kp, *vp, *attp, *hp;
    float *bfv;
    cudaGetSymbolAddress((void**)&d1p,   g_d1p);
    cudaGetSymbolAddress((void**)&d2p,   g_d2p);
    cudaGetSymbolAddress((void**)&wqp,   g_wqp);
    cudaGetSymbolAddress((void**)&wkp,   g_wkp);
    cudaGetSymbolAddress((void**)&wvp,   g_wvp);
    cudaGetSymbolAddress((void**)&wc2p,  g_wc2p);
    cudaGetSymbolAddress((void**)&wfp,   g_wfp);
    cudaGetSymbolAddress((void**)&wc1bp, g_wc1bp);
    cudaGetSymbolAddress((void**)&wmp,   g_wmp);
    cudaGetSymbolAddress((void**)&bfv,   g_bfv);
    cudaGetSymbolAddress((void**)&qp,    g_qp);
    cudaGetSymbolAddress((void**)&kp,    g_kp);
    cudaGetSymbolAddress((void**)&vp,    g_vp);
    cudaGetSymbolAddress((void**)&attp,  g_attp);
    cudaGetSymbolAddress((void**)&hp,    g_hp);

    cudaFuncSetAttribute(gemm_qkv,  cudaFuncAttributeMaxDynamicSharedMemorySize, GEMM_SMEM_H);
    cudaFuncSetAttribute(gemm_h<2>, cudaFuncAttributeMaxDynamicSharedMemorySize, GEMM_SMEM_H);
    cudaFuncSetAttribute(gemm_h<3>, cudaFuncAttributeMaxDynamicSharedMemorySize, GEMM_SMEM_H);
    cudaFuncSetAttribute(attn_bf16, cudaFuncAttributeMaxDynamicSharedMemorySize, ATT_SMEM);

    // 0) fp16 pair-pack conversions (perm16 on weights) + fused bias
    prepass<<<4226, 256>>>(desc1, desc2, Wq, Wk, Wv, Wc2, Wc1, Wm, bm, bc1,
                           d1p, d2p, wqp, wkp, wvp, wc2p, wfp, wc1bp, wmp, bfv);

    // 1) Q/K/V projections (fp16, 3-stage) + Wf2 prep GEMM (z = 24)
    gemm_qkv<<<dim3(N_/128, C_/64, 25), 128, GEMM_SMEM_H>>>(
        wqp, bq, wkp, bk, wvp, bv, d1p, d2p, wv, qp, kp, vp, wc1bp, wmp, wfp);

    // 2) attention (bf16), fp16-pair output
    attn_bf16<<<dim3(N_/128, B_*4), 128, ATT_SMEM>>>(qp, kp, vp, attp);

    // 3) fused (Wc1 ∘ [I; Wm]) + BN + ReLU -> h (fp16 pairs)
    gemm_h<2><<<dim3(N_/128, 8, B_), 128, GEMM_SMEM_H>>>(
        wfp, bfv, d1p, attp, nullptr, hp, 2*C_, 256, 128,
        gamma, beta, mean, var);

    // 4) Wc2 + residual -> out (fp32)
    gemm_h<3><<<dim3(N_/128, 4, B_), 128, GEMM_SMEM_H>>>(
        wc2p, bc2, hp, hp, out, nullptr, C_, 256, 256,
        desc1, nullptr, nullptr, nullptr);
}